// round 11
// baseline (speedup 1.0000x reference)
#include <cuda_runtime.h>

// FeatureSim: attn[b,i,j] = softmax_j( sum_k w[k]*|x[b,i,k]-x[b,j,k]| ), mask j < len[b].
// B=8, L=1024, F=16 (first 11 used), out f32 [8,1024,1024].
//
// R11: R10's scalar-FFMA core at C=2 cols/thread, TPB=512, 2 blocks/SM -> occ 50%.
//      Same instr/element as R10 (LDS broadcasts shared; fma work scales), but
//      kk drops 44->22 regs so occupancy goes 34% -> 50% (8 warps/SMSP) for
//      latency hiding. R6's C=2 attempt failed because its f32x2+LOP3 core was
//      2x the instructions; the scalar core is lean.
//      - compute: 3 LDS.128/row + 44 FADD/FFMA (free |.|/- modifiers) + 2 ex2
//        + STS.64 to the e-slab.
//      - epilogue: 2 warps per row, each owns a 512-col half: 4 LDS.128 -> sum
//        -> butterfly -> red[row][half]; barrier; combine + rcp; scale the
//        already-loaded registers -> STG. 3 barriers total.

#define L_SEQ 1024
#define FDIM  16
#define NF    11
#define BQ    8             // rows per block
#define TPB   512           // each thread owns 2 consecutive key columns
#define BPB   (L_SEQ / BQ)  // 128 blocks per batch

__device__ __forceinline__ float ex2(float a) {
    float r; asm("ex2.approx.f32 %0, %1;" : "=f"(r) : "f"(a)); return r;
}

#define LOG2E 1.4426950408889634f

__global__ __launch_bounds__(TPB, 2)
void featsim_kernel(const float* __restrict__ x,
                    const int*   __restrict__ lens,
                    const float* __restrict__ w,
                    float*       __restrict__ out)
{
    const int b    = blockIdx.x / BPB;
    const int rb   = blockIdx.x % BPB;
    const int i0   = rb * BQ;
    const int tid  = threadIdx.x;
    const int lane = tid & 31;
    const int warp = tid >> 5;          // 0..15
    const int j0   = tid * 2;

    __shared__ __align__(16) float sq[BQ][12];      // raw queries (11 used, pad 0)
    __shared__ __align__(16) float se[BQ][L_SEQ];   // unnormalized e staging (32 KB)
    __shared__ float red[BQ][2];                    // half-row partial sums

    // Signed per-feature scale wl_k = w_k * log2e (|d| via free abs modifier).
    float wl[NF];
#pragma unroll
    for (int k = 0; k < NF; ++k) wl[k] = w[k] * LOG2E;

    // Stage raw queries.
    if (tid < BQ * 12) {
        int r = tid / 12, k = tid - r * 12;
        sq[r][k] = (k < NF) ? x[(size_t)(b * L_SEQ + i0 + r) * FDIM + k] : 0.f;
    }

    // Keys: 2 cols, raw floats straight from LDG (L2-resident).
    float kk[2][NF];
#pragma unroll
    for (int cc = 0; cc < 2; ++cc) {
        const float4* kp = reinterpret_cast<const float4*>(
            x + (size_t)(b * L_SEQ + j0 + cc) * FDIM);
        float4 a = kp[0], c = kp[1], d = kp[2];
        kk[cc][0] = a.x;  kk[cc][1] = a.y;  kk[cc][2]  = a.z;  kk[cc][3] = a.w;
        kk[cc][4] = c.x;  kk[cc][5] = c.y;  kk[cc][6]  = c.z;  kk[cc][7] = c.w;
        kk[cc][8] = d.x;  kk[cc][9] = d.y;  kk[cc][10] = d.z;
    }

    // Key-mask as accumulator bias: invalid col -> -1e30 -> ex2 -> exact 0.
    const int len = lens[b];
    const float bias0 = (j0 + 0 < len) ? 0.f : -1e30f;
    const float bias1 = (j0 + 1 < len) ? 0.f : -1e30f;

    __syncthreads();

    // ---- compute: 3 LDS.128/row + 44 FADD/FFMA + 2 ex2 + STS.64 ----
#pragma unroll
    for (int r = 0; r < BQ; ++r) {
        const float4* qp = reinterpret_cast<const float4*>(sq[r]);
        float4 qa = qp[0];              // features 0..3
        float4 qb = qp[1];              // features 4..7
        float4 qc = qp[2];              // features 8..10 (+pad)
        const float qs[NF] = { qa.x, qa.y, qa.z, qa.w,
                               qb.x, qb.y, qb.z, qb.w,
                               qc.x, qc.y, qc.z };

        float s0 = bias0, s1 = bias1;
#pragma unroll
        for (int k = 0; k < NF; ++k) {
            const float q = qs[k], wk = wl[k];
            s0 = fmaf(fabsf(q - kk[0][k]), wk, s0);
            s1 = fmaf(fabsf(q - kk[1][k]), wk, s1);
        }

        *reinterpret_cast<float2*>(&se[r][j0]) = make_float2(ex2(s0), ex2(s1));
    }
    __syncthreads();

    // ---- epilogue: 2 warps per row; each owns a 512-col half ----
    {
        const int row  = warp >> 1;
        const int half = warp & 1;
        const int base = half * 512 + lane * 4;

        float4 v[4];
        float acc = 0.f;
#pragma unroll
        for (int p = 0; p < 4; ++p) {
            v[p] = *reinterpret_cast<float4*>(&se[row][base + p * 128]);
            acc += (v[p].x + v[p].y) + (v[p].z + v[p].w);
        }
#pragma unroll
        for (int o = 16; o > 0; o >>= 1)
            acc += __shfl_xor_sync(0xffffffffu, acc, o);
        if (lane == 0) red[row][half] = acc;
        __syncthreads();

        float tot = red[row][0] + red[row][1];      // broadcast LDS
        float inv; asm("rcp.approx.f32 %0, %1;" : "=f"(inv) : "f"(tot)); // len>=1 => tot>0

        float4* orow = reinterpret_cast<float4*>(
            out + (size_t)(b * L_SEQ + i0 + row) * L_SEQ + half * 512);
#pragma unroll
        for (int p = 0; p < 4; ++p) {
            orow[p * 32 + lane] =
                make_float4(v[p].x * inv, v[p].y * inv, v[p].z * inv, v[p].w * inv);
        }
    }
}

extern "C" void kernel_launch(void* const* d_in, const int* in_sizes, int n_in,
                              void* d_out, int out_size)
{
    const float* x    = (const float*)d_in[0];   // [8,1024,16] f32
    const int*   lens = (const int*)d_in[1];     // [8] i32
    const float* w    = (const float*)d_in[2];   // [11] f32
    float*       out  = (float*)d_out;           // [8,1024,1024] f32

    dim3 grid(8 * BPB);   // 1024 blocks
    dim3 block(TPB);
    featsim_kernel<<<grid, block>>>(x, lens, w, out);
}